// round 1
// baseline (speedup 1.0000x reference)
#include <cuda_runtime.h>
#include <math.h>

// Problem constants
#define S_LEN 2048
#define BH 64           // B*H = 4*16
#define DQ 64
#define DP 32
#define PAD 100         // padded smem row stride (floats) for 96-dim inner axis
#define BM 128
#define BN 128

#define SCALE_Q 0.125f                 // 64^-0.5
#define SCALE_P 0.17677669529663687f   // 32^-0.5

__device__ __forceinline__ float clamp5(float x) {
    return fminf(fmaxf(x, -5.0f), 5.0f);
}

// ---------------------------------------------------------------------------
// Pass A: batched score GEMM.
// C[bh][m][n] = sum_d  Acat[m][d] * Bcat[n][d]   (d = 0..95)
//   Acat = [clamp(q)*SCALE_Q | clamp(pq)*SCALE_P]  (scales folded into Q side)
//   Bcat = [clamp(k)         | clamp(pk)        ]
// 128x128 tile per CTA, full K=96 in one shot (no k-loop), 8x8 micro-tiles.
// ---------------------------------------------------------------------------
__global__ __launch_bounds__(256, 1) void score_gemm(
    const float* __restrict__ keys, const float* __restrict__ queries,
    const float* __restrict__ pos_key, const float* __restrict__ pos_query,
    float* __restrict__ out)
{
    extern __shared__ float sm[];
    float* As = sm;              // [BM][PAD]
    float* Bs = sm + BM * PAD;   // [BN][PAD]

    const int tid = threadIdx.x;
    const int bh = blockIdx.z;
    const int mbase = blockIdx.y * BM;
    const int nbase = blockIdx.x * BN;

    const float* qptr  = queries   + (size_t)bh * S_LEN * DQ;
    const float* pqptr = pos_query + (size_t)bh * S_LEN * DP;
    const float* kptr  = keys      + (size_t)bh * S_LEN * DQ;
    const float* pkptr = pos_key   + (size_t)bh * S_LEN * DP;

    // Load A tile: 128 rows x 96 floats = 3072 float4, 12 per thread.
    #pragma unroll
    for (int it = 0; it < 12; it++) {
        int f4 = tid + it * 256;
        int m  = f4 / 24;        // 24 float4 per 96-float row
        int d4 = f4 % 24;
        float4 v;
        if (d4 < 16) {
            v = *(const float4*)(qptr + (size_t)(mbase + m) * DQ + d4 * 4);
            v.x = clamp5(v.x) * SCALE_Q; v.y = clamp5(v.y) * SCALE_Q;
            v.z = clamp5(v.z) * SCALE_Q; v.w = clamp5(v.w) * SCALE_Q;
        } else {
            v = *(const float4*)(pqptr + (size_t)(mbase + m) * DP + (d4 - 16) * 4);
            v.x = clamp5(v.x) * SCALE_P; v.y = clamp5(v.y) * SCALE_P;
            v.z = clamp5(v.z) * SCALE_P; v.w = clamp5(v.w) * SCALE_P;
        }
        *(float4*)(As + m * PAD + d4 * 4) = v;
    }
    // Load B tile (keys side: clamp only, no scale).
    #pragma unroll
    for (int it = 0; it < 12; it++) {
        int f4 = tid + it * 256;
        int n  = f4 / 24;
        int d4 = f4 % 24;
        float4 v;
        if (d4 < 16) {
            v = *(const float4*)(kptr + (size_t)(nbase + n) * DQ + d4 * 4);
        } else {
            v = *(const float4*)(pkptr + (size_t)(nbase + n) * DP + (d4 - 16) * 4);
        }
        v.x = clamp5(v.x); v.y = clamp5(v.y); v.z = clamp5(v.z); v.w = clamp5(v.w);
        *(float4*)(Bs + n * PAD + d4 * 4) = v;
    }
    __syncthreads();

    const int tx = tid & 15;   // n-dim: n = nbase + j*16 + tx  (coalesced stores)
    const int ty = tid >> 4;   // m-dim: m = mbase + i*16 + ty

    float acc[8][8];
    #pragma unroll
    for (int i = 0; i < 8; i++)
        #pragma unroll
        for (int j = 0; j < 8; j++) acc[i][j] = 0.0f;

    #pragma unroll 2
    for (int d4 = 0; d4 < 24; d4++) {
        float4 a[8], b[8];
        #pragma unroll
        for (int i = 0; i < 8; i++)
            a[i] = *(const float4*)(As + (i * 16 + ty) * PAD + d4 * 4);
        #pragma unroll
        for (int j = 0; j < 8; j++)
            b[j] = *(const float4*)(Bs + (j * 16 + tx) * PAD + d4 * 4);
        #pragma unroll
        for (int i = 0; i < 8; i++) {
            #pragma unroll
            for (int j = 0; j < 8; j++) {
                acc[i][j] = fmaf(a[i].x, b[j].x, acc[i][j]);
                acc[i][j] = fmaf(a[i].y, b[j].y, acc[i][j]);
                acc[i][j] = fmaf(a[i].z, b[j].z, acc[i][j]);
                acc[i][j] = fmaf(a[i].w, b[j].w, acc[i][j]);
            }
        }
    }

    // Epilogue: scalar stores, lane-contiguous (n = j*16 + tx).
    #pragma unroll
    for (int i = 0; i < 8; i++) {
        int row = mbase + i * 16 + ty;
        float* o = out + ((size_t)bh * S_LEN + row) * S_LEN + nbase;
        #pragma unroll
        for (int j = 0; j < 8; j++) {
            o[j * 16 + tx] = acc[i][j];
        }
    }
}

// ---------------------------------------------------------------------------
// Pass B: in-place row softmax. One CTA per row (2048 floats, 8 per thread).
// exp via pure-FMA exp2 polynomial: avoids MUFU.EX2 (rt_SMSP=8 on B300 would
// make 268M expf calls cost ~1.9ms; poly is ~13 FMA -> negligible).
// ---------------------------------------------------------------------------
__device__ __forceinline__ float fast_exp_nonpos(float x) {
    // exact enough for x <= 0 (rel err ~1e-7); underflow -> 0.
    float y = x * 1.4426950408889634f;     // log2(e)
    float n = rintf(y);
    float f = y - n;                        // f in [-0.5, 0.5]
    float p = 1.5403530393e-4f;
    p = fmaf(p, f, 1.3333558146e-3f);
    p = fmaf(p, f, 9.6181291076e-3f);
    p = fmaf(p, f, 5.5504108664e-2f);
    p = fmaf(p, f, 2.4022650696e-1f);
    p = fmaf(p, f, 6.9314718056e-1f);
    p = fmaf(p, f, 1.0f);
    int e = (int)n + 127;                   // n <= 0 -> e <= 127
    float s = (e > 0) ? __int_as_float(e << 23) : 0.0f;
    return p * s;
}

__global__ __launch_bounds__(256, 1) void softmax_rows(float* __restrict__ out)
{
    __shared__ float red[8];
    float* p = out + (size_t)blockIdx.x * S_LEN;
    const int tid = threadIdx.x;
    const int lane = tid & 31;
    const int warp = tid >> 5;

    float4* p4 = (float4*)p;
    float4 v0 = p4[tid];
    float4 v1 = p4[tid + 256];

    // --- max ---
    float m = fmaxf(fmaxf(fmaxf(v0.x, v0.y), fmaxf(v0.z, v0.w)),
                    fmaxf(fmaxf(v1.x, v1.y), fmaxf(v1.z, v1.w)));
    #pragma unroll
    for (int o = 16; o > 0; o >>= 1)
        m = fmaxf(m, __shfl_xor_sync(0xffffffffu, m, o));
    if (lane == 0) red[warp] = m;
    __syncthreads();
    float M = red[0];
    #pragma unroll
    for (int i = 1; i < 8; i++) M = fmaxf(M, red[i]);
    __syncthreads();

    // --- exp + sum ---
    v0.x = fast_exp_nonpos(v0.x - M); v0.y = fast_exp_nonpos(v0.y - M);
    v0.z = fast_exp_nonpos(v0.z - M); v0.w = fast_exp_nonpos(v0.w - M);
    v1.x = fast_exp_nonpos(v1.x - M); v1.y = fast_exp_nonpos(v1.y - M);
    v1.z = fast_exp_nonpos(v1.z - M); v1.w = fast_exp_nonpos(v1.w - M);

    float s = ((v0.x + v0.y) + (v0.z + v0.w)) + ((v1.x + v1.y) + (v1.z + v1.w));
    #pragma unroll
    for (int o = 16; o > 0; o >>= 1)
        s += __shfl_xor_sync(0xffffffffu, s, o);
    if (lane == 0) red[warp] = s;
    __syncthreads();
    float Ssum = 0.0f;
    #pragma unroll
    for (int i = 0; i < 8; i++) Ssum += red[i];

    float inv = 1.0f / Ssum;   // Ssum >= 1 (max element contributes 1)
    v0.x *= inv; v0.y *= inv; v0.z *= inv; v0.w *= inv;
    v1.x *= inv; v1.y *= inv; v1.z *= inv; v1.w *= inv;
    p4[tid] = v0;
    p4[tid + 256] = v1;
}

// ---------------------------------------------------------------------------
extern "C" void kernel_launch(void* const* d_in, const int* in_sizes, int n_in,
                              void* d_out, int out_size)
{
    const float* keys      = (const float*)d_in[0];
    const float* queries   = (const float*)d_in[1];
    const float* pos_key   = (const float*)d_in[2];
    const float* pos_query = (const float*)d_in[3];
    float* out = (float*)d_out;

    const int smem = 2 * BM * PAD * sizeof(float);   // 102400 B
    cudaFuncSetAttribute(score_gemm, cudaFuncAttributeMaxDynamicSharedMemorySize, smem);

    dim3 grid(S_LEN / BN, S_LEN / BM, BH);   // (16, 16, 64)
    score_gemm<<<grid, 256, smem>>>(keys, queries, pos_key, pos_query, out);

    softmax_rows<<<BH * S_LEN, 256>>>(out);   // 131072 rows
}

// round 4
// speedup vs baseline: 1.4512x; 1.4512x over previous
#include <cuda_runtime.h>
#include <cuda_bf16.h>
#include <cstdint>
#include <math.h>

// ---------------- problem constants ----------------
#define S_LEN 2048
#define BHN   64          // B*H
#define DQ    64
#define DP    32
#define KC    96          // concatenated K (q|pq)
#define K2    192         // hi || lo
#define TM    128
#define TN    128
#define SPAD  200         // smem row stride in bf16 elements (400 B, conflict-free)
#define SCALE_Q 0.125f
#define SCALE_P 0.17677669529663687f

// bf16 split scratch: [bh][s][192]  (cols 0-95 = hi, 96-191 = lo)
__device__ __align__(16) __nv_bfloat16 g_A2[(size_t)BHN * S_LEN * K2];
__device__ __align__(16) __nv_bfloat16 g_B2[(size_t)BHN * S_LEN * K2];

__device__ __forceinline__ float clamp5(float x) {
    return fminf(fmaxf(x, -5.0f), 5.0f);
}

__device__ __forceinline__ uint32_t smem_u32(const void* p) {
    uint32_t a;
    asm("{ .reg .u64 t; cvta.to.shared.u64 t, %1; cvt.u32.u64 %0, t; }" : "=r"(a) : "l"(p));
    return a;
}

__device__ __forceinline__ void cp16(uint32_t dst, const void* src) {
    asm volatile("cp.async.cg.shared.global [%0], [%1], 16;" :: "r"(dst), "l"(src));
}
#define CP_COMMIT() asm volatile("cp.async.commit_group;" ::: "memory")
#define CP_WAIT0()  asm volatile("cp.async.wait_group 0;" ::: "memory")

__device__ __forceinline__ void ldsm_x4(uint32_t* r, uint32_t addr) {
    asm volatile("ldmatrix.sync.aligned.m8n8.x4.shared.b16 {%0,%1,%2,%3}, [%4];"
                 : "=r"(r[0]), "=r"(r[1]), "=r"(r[2]), "=r"(r[3]) : "r"(addr));
}
__device__ __forceinline__ void ldsm_x2(uint32_t* r, uint32_t addr) {
    asm volatile("ldmatrix.sync.aligned.m8n8.x2.shared.b16 {%0,%1}, [%2];"
                 : "=r"(r[0]), "=r"(r[1]) : "r"(addr));
}
__device__ __forceinline__ void mma_bf16(float* d, const uint32_t* a, const uint32_t* b) {
    asm volatile("mma.sync.aligned.m16n8k16.row.col.f32.bf16.bf16.f32 "
                 "{%0,%1,%2,%3}, {%4,%5,%6,%7}, {%8,%9}, {%0,%1,%2,%3};"
                 : "+f"(d[0]), "+f"(d[1]), "+f"(d[2]), "+f"(d[3])
                 : "r"(a[0]), "r"(a[1]), "r"(a[2]), "r"(a[3]), "r"(b[0]), "r"(b[1]));
}

// ---------------------------------------------------------------------------
// Pass 0: clamp + scale + bf16 hi/lo split into K-concatenated scratch.
// ---------------------------------------------------------------------------
__global__ __launch_bounds__(256) void prep_split(
    const float* __restrict__ keys, const float* __restrict__ queries,
    const float* __restrict__ pos_key, const float* __restrict__ pos_query)
{
    size_t idx = (size_t)blockIdx.x * blockDim.x + threadIdx.x;
    const size_t total = (size_t)BHN * S_LEN * KC;
    if (idx >= total) return;
    size_t row = idx / KC;
    int c = (int)(idx % KC);
    float a, b;
    if (c < DQ) {
        a = clamp5(queries[row * DQ + c]) * SCALE_Q;
        b = clamp5(keys[row * DQ + c]);
    } else {
        a = clamp5(pos_query[row * DP + (c - DQ)]) * SCALE_P;
        b = clamp5(pos_key[row * DP + (c - DQ)]);
    }
    __nv_bfloat16 ah = __float2bfloat16_rn(a);
    __nv_bfloat16 al = __float2bfloat16_rn(a - __bfloat162float(ah));
    __nv_bfloat16 bhv = __float2bfloat16_rn(b);
    __nv_bfloat16 bl = __float2bfloat16_rn(b - __bfloat162float(bhv));
    g_A2[row * K2 + c] = ah;  g_A2[row * K2 + KC + c] = al;
    g_B2[row * K2 + c] = bhv; g_B2[row * K2 + KC + c] = bl;
}

// ---------------------------------------------------------------------------
// Pass 1: HMMA score GEMM, 3-product split:
//   C = Ah.Bh + Ah.Bl + Al.Bh    (Al.Bl dropped, ~2^-18)
// 128x128 CTA tile, 8 warps (2x4), warp tile 64x32, whole [hi|lo] K=192
// staged once in smem; 18 k-steps indexing (ka, kb) pairs.
// ---------------------------------------------------------------------------
__global__ __launch_bounds__(256, 2) void score_gemm_hmma(float* __restrict__ out)
{
    extern __shared__ __align__(16) char smraw[];
    __nv_bfloat16* As = (__nv_bfloat16*)smraw;          // [TM][SPAD]
    __nv_bfloat16* Bs = As + TM * SPAD;                 // [TN][SPAD]

    const int tid = threadIdx.x;
    const int lane = tid & 31, warp = tid >> 5;
    const int wm = warp & 1, wn = warp >> 1;            // 2 x 4 warp grid
    const int nt = blockIdx.x, mt = blockIdx.y, bh = blockIdx.z;

    const __nv_bfloat16* Ag = g_A2 + ((size_t)bh * S_LEN + (size_t)mt * TM) * K2;
    const __nv_bfloat16* Bg = g_B2 + ((size_t)bh * S_LEN + (size_t)nt * TN) * K2;

    const uint32_t sA = smem_u32(As), sB = smem_u32(Bs);

    // stage full tiles: 128 rows x 24 chunks(16B) each, 12 chunks/thread/tile
    #pragma unroll
    for (int it = 0; it < 12; it++) {
        int f = tid + it * 256;
        int row = f / 24, c = f % 24;
        cp16(sA + row * (SPAD * 2) + c * 16, (const char*)Ag + (size_t)row * (K2 * 2) + c * 16);
        cp16(sB + row * (SPAD * 2) + c * 16, (const char*)Bg + (size_t)row * (K2 * 2) + c * 16);
    }
    CP_COMMIT();
    CP_WAIT0();
    __syncthreads();

    float acc[4][4][4];
    #pragma unroll
    for (int i = 0; i < 4; i++)
        #pragma unroll
        for (int j = 0; j < 4; j++)
            #pragma unroll
            for (int v = 0; v < 4; v++) acc[i][j][v] = 0.0f;

    // ldmatrix base addresses (per-lane row; k offset varies per step)
    const int a_row = wm * 64 + (lane & 15);            // + mf*16
    const int a_koff = (lane >> 4) << 3;                // 0 or 8
    const int b_row = wn * 32 + (lane & 7);             // + nf*8
    const int b_koff = ((lane >> 3) & 1) << 3;          // 0 or 8

    // 3-product schedule: (ka, kb) per step
    const int KAs[18] = { 0,16,32,48,64,80,  0,16,32,48,64,80, 96,112,128,144,160,176 };
    const int KBs[18] = { 0,16,32,48,64,80, 96,112,128,144,160,176,  0,16,32,48,64,80 };

    #pragma unroll
    for (int s = 0; s < 18; s++) {
        const int ka = KAs[s], kb = KBs[s];
        uint32_t a[4][4], b[4][2];
        #pragma unroll
        for (int mf = 0; mf < 4; mf++)
            ldsm_x4(a[mf], sA + (a_row + mf * 16) * (SPAD * 2) + (ka + a_koff) * 2);
        #pragma unroll
        for (int nf = 0; nf < 4; nf++)
            ldsm_x2(b[nf], sB + (b_row + nf * 8) * (SPAD * 2) + (kb + b_koff) * 2);
        #pragma unroll
        for (int mf = 0; mf < 4; mf++)
            #pragma unroll
            for (int nf = 0; nf < 4; nf++)
                mma_bf16(acc[mf][nf], a[mf], b[nf]);
    }

    // epilogue: float2 stores (lane quads cover 32B sectors)
    const int r = lane >> 2, c2 = (lane & 3) * 2;
    #pragma unroll
    for (int mf = 0; mf < 4; mf++) {
        size_t row_g = (size_t)bh * S_LEN + (size_t)mt * TM + wm * 64 + mf * 16 + r;
        #pragma unroll
        for (int nf = 0; nf < 4; nf++) {
            size_t col_g = (size_t)nt * TN + wn * 32 + nf * 8 + c2;
            *(float2*)(out + row_g * S_LEN + col_g) =
                make_float2(acc[mf][nf][0], acc[mf][nf][1]);
            *(float2*)(out + (row_g + 8) * S_LEN + col_g) =
                make_float2(acc[mf][nf][2], acc[mf][nf][3]);
        }
    }
}

// ---------------------------------------------------------------------------
// Pass 2: in-place row softmax (R1-proven: 88% DRAM, near roofline).
// ---------------------------------------------------------------------------
__device__ __forceinline__ float fast_exp_nonpos(float x) {
    float y = x * 1.4426950408889634f;
    float n = rintf(y);
    float f = y - n;
    float p = 1.5403530393e-4f;
    p = fmaf(p, f, 1.3333558146e-3f);
    p = fmaf(p, f, 9.6181291076e-3f);
    p = fmaf(p, f, 5.5504108664e-2f);
    p = fmaf(p, f, 2.4022650696e-1f);
    p = fmaf(p, f, 6.9314718056e-1f);
    p = fmaf(p, f, 1.0f);
    int e = (int)n + 127;
    float s = (e > 0) ? __int_as_float(e << 23) : 0.0f;
    return p * s;
}

__global__ __launch_bounds__(256, 1) void softmax_rows(float* __restrict__ out)
{
    __shared__ float red[8];
    float* p = out + (size_t)blockIdx.x * S_LEN;
    const int tid = threadIdx.x;
    const int lane = tid & 31;
    const int warp = tid >> 5;

    float4* p4 = (float4*)p;
    float4 v0 = p4[tid];
    float4 v1 = p4[tid + 256];

    float m = fmaxf(fmaxf(fmaxf(v0.x, v0.y), fmaxf(v0.z, v0.w)),
                    fmaxf(fmaxf(v1.x, v1.y), fmaxf(v1.z, v1.w)));
    #pragma unroll
    for (int o = 16; o > 0; o >>= 1)
        m = fmaxf(m, __shfl_xor_sync(0xffffffffu, m, o));
    if (lane == 0) red[warp] = m;
    __syncthreads();
    float M = red[0];
    #pragma unroll
    for (int i = 1; i < 8; i++) M = fmaxf(M, red[i]);
    __syncthreads();

    v0.x = fast_exp_nonpos(v0.x - M); v0.y = fast_exp_nonpos(v0.y - M);
    v0.z = fast_exp_nonpos(v0.z - M); v0.w = fast_exp_nonpos(v0.w - M);
    v1.x = fast_exp_nonpos(v1.x - M); v1.y = fast_exp_nonpos(v1.y - M);
    v1.z = fast_exp_nonpos(v1.z - M); v1.w = fast_exp_nonpos(v1.w - M);

    float s = ((v0.x + v0.y) + (v0.z + v0.w)) + ((v1.x + v1.y) + (v1.z + v1.w));
    #pragma unroll
    for (int o = 16; o > 0; o >>= 1)
        s += __shfl_xor_sync(0xffffffffu, s, o);
    if (lane == 0) red[warp] = s;
    __syncthreads();
    float Ssum = 0.0f;
    #pragma unroll
    for (int i = 0; i < 8; i++) Ssum += red[i];

    float inv = 1.0f / Ssum;
    v0.x *= inv; v0.y *= inv; v0.z *= inv; v0.w *= inv;
    v1.x *= inv; v1.y *= inv; v1.z *= inv; v1.w *= inv;
    p4[tid] = v0;
    p4[tid + 256] = v1;
}

// ---------------------------------------------------------------------------
extern "C" void kernel_launch(void* const* d_in, const int* in_sizes, int n_in,
                              void* d_out, int out_size)
{
    const float* keys      = (const float*)d_in[0];
    const float* queries   = (const float*)d_in[1];
    const float* pos_key   = (const float*)d_in[2];
    const float* pos_query = (const float*)d_in[3];
    float* out = (float*)d_out;

    // pass 0: split
    const size_t prep_total = (size_t)BHN * S_LEN * KC;
    prep_split<<<(unsigned)((prep_total + 255) / 256), 256>>>(keys, queries, pos_key, pos_query);

    // pass 1: HMMA GEMM (3-product split)
    const int smem = 2 * TM * SPAD * sizeof(__nv_bfloat16);   // 102400 B
    cudaFuncSetAttribute(score_gemm_hmma, cudaFuncAttributeMaxDynamicSharedMemorySize, smem);
    dim3 g(S_LEN / TN, S_LEN / TM, BHN);    // (16, 16, 64)
    score_gemm_hmma<<<g, 256, smem>>>(out);

    // pass 2: softmax
    softmax_rows<<<BHN * S_LEN, 256>>>(out);
}

// round 5
// speedup vs baseline: 2.5115x; 1.7306x over previous
#include <cuda_runtime.h>
#include <cuda_fp16.h>
#include <cstdint>
#include <math.h>

// ---------------- problem constants ----------------
#define S_LEN 2048
#define BHN   64          // B*H
#define DQ    64
#define DP    32
#define KC    96          // concatenated K (q|pq)
#define TM    128
#define TN    128
#define SPAD  104         // smem row stride in halves (208 B = 13*16, conflict-free)
#define SCALE_Q 0.125f
#define SCALE_P 0.17677669529663687f

// fp16 scratch: [bh][s][96]  (clamped + scaled on A side)
__device__ __align__(16) __half g_Ah[(size_t)BHN * S_LEN * KC];
__device__ __align__(16) __half g_Bh[(size_t)BHN * S_LEN * KC];

__device__ __forceinline__ float clamp5(float x) {
    return fminf(fmaxf(x, -5.0f), 5.0f);
}

__device__ __forceinline__ uint32_t smem_u32(const void* p) {
    uint32_t a;
    asm("{ .reg .u64 t; cvta.to.shared.u64 t, %1; cvt.u32.u64 %0, t; }" : "=r"(a) : "l"(p));
    return a;
}

__device__ __forceinline__ void cp16(uint32_t dst, const void* src) {
    asm volatile("cp.async.cg.shared.global [%0], [%1], 16;" :: "r"(dst), "l"(src));
}
#define CP_COMMIT() asm volatile("cp.async.commit_group;" ::: "memory")
#define CP_WAIT0()  asm volatile("cp.async.wait_group 0;" ::: "memory")

__device__ __forceinline__ void ldsm_x4(uint32_t* r, uint32_t addr) {
    asm volatile("ldmatrix.sync.aligned.m8n8.x4.shared.b16 {%0,%1,%2,%3}, [%4];"
                 : "=r"(r[0]), "=r"(r[1]), "=r"(r[2]), "=r"(r[3]) : "r"(addr));
}
__device__ __forceinline__ void ldsm_x2(uint32_t* r, uint32_t addr) {
    asm volatile("ldmatrix.sync.aligned.m8n8.x2.shared.b16 {%0,%1}, [%2];"
                 : "=r"(r[0]), "=r"(r[1]) : "r"(addr));
}
__device__ __forceinline__ void mma_fp16(float* d, const uint32_t* a, const uint32_t* b) {
    asm volatile("mma.sync.aligned.m16n8k16.row.col.f32.f16.f16.f32 "
                 "{%0,%1,%2,%3}, {%4,%5,%6,%7}, {%8,%9}, {%0,%1,%2,%3};"
                 : "+f"(d[0]), "+f"(d[1]), "+f"(d[2]), "+f"(d[3])
                 : "r"(a[0]), "r"(a[1]), "r"(a[2]), "r"(a[3]), "r"(b[0]), "r"(b[1]));
}

// ---------------------------------------------------------------------------
// Pass 0: clamp + scale + fp16 convert into K-concatenated scratch.
// ---------------------------------------------------------------------------
__global__ __launch_bounds__(256) void prep_fp16(
    const float* __restrict__ keys, const float* __restrict__ queries,
    const float* __restrict__ pos_key, const float* __restrict__ pos_query)
{
    size_t idx = (size_t)blockIdx.x * blockDim.x + threadIdx.x;
    const size_t total = (size_t)BHN * S_LEN * KC;
    if (idx >= total) return;
    size_t row = idx / KC;
    int c = (int)(idx % KC);
    float a, b;
    if (c < DQ) {
        a = clamp5(queries[row * DQ + c]) * SCALE_Q;
        b = clamp5(keys[row * DQ + c]);
    } else {
        a = clamp5(pos_query[row * DP + (c - DQ)]) * SCALE_P;
        b = clamp5(pos_key[row * DP + (c - DQ)]);
    }
    g_Ah[idx] = __float2half_rn(a);
    g_Bh[idx] = __float2half_rn(b);
}

// ---------------------------------------------------------------------------
// Pass 1: fp16 HMMA score GEMM, K=96 single product.
// 128x128 CTA tile, 8 warps (2x4), warp tile 64x32, whole K in smem once;
// 6 k-steps of 16.
// ---------------------------------------------------------------------------
__global__ __launch_bounds__(256, 2) void score_gemm_hmma(float* __restrict__ out)
{
    extern __shared__ __align__(16) char smraw[];
    __half* As = (__half*)smraw;            // [TM][SPAD]
    __half* Bs = As + TM * SPAD;            // [TN][SPAD]

    const int tid = threadIdx.x;
    const int lane = tid & 31, warp = tid >> 5;
    const int wm = warp & 1, wn = warp >> 1;            // 2 x 4 warp grid
    const int nt = blockIdx.x, mt = blockIdx.y, bh = blockIdx.z;

    const __half* Ag = g_Ah + ((size_t)bh * S_LEN + (size_t)mt * TM) * KC;
    const __half* Bg = g_Bh + ((size_t)bh * S_LEN + (size_t)nt * TN) * KC;

    const uint32_t sA = smem_u32(As), sB = smem_u32(Bs);

    // stage tiles: 128 rows x 12 chunks(16B) each; 6 chunks/thread/tile
    #pragma unroll
    for (int it = 0; it < 6; it++) {
        int f = tid + it * 256;
        int row = f / 12, c = f % 12;
        cp16(sA + row * (SPAD * 2) + c * 16, (const char*)Ag + (size_t)row * (KC * 2) + c * 16);
        cp16(sB + row * (SPAD * 2) + c * 16, (const char*)Bg + (size_t)row * (KC * 2) + c * 16);
    }
    CP_COMMIT();
    CP_WAIT0();
    __syncthreads();

    float acc[4][4][4];
    #pragma unroll
    for (int i = 0; i < 4; i++)
        #pragma unroll
        for (int j = 0; j < 4; j++)
            #pragma unroll
            for (int v = 0; v < 4; v++) acc[i][j][v] = 0.0f;

    // ldmatrix base addresses
    const int a_row = wm * 64 + (lane & 15);            // + mf*16
    const int a_koff = (lane >> 4) << 3;                // 0 or 8
    const int b_row = wn * 32 + (lane & 7);             // + nf*8
    const int b_koff = ((lane >> 3) & 1) << 3;          // 0 or 8

    #pragma unroll
    for (int s = 0; s < 6; s++) {
        const int k0 = s * 16;
        uint32_t a[4][4], b[4][2];
        #pragma unroll
        for (int mf = 0; mf < 4; mf++)
            ldsm_x4(a[mf], sA + (a_row + mf * 16) * (SPAD * 2) + (k0 + a_koff) * 2);
        #pragma unroll
        for (int nf = 0; nf < 4; nf++)
            ldsm_x2(b[nf], sB + (b_row + nf * 8) * (SPAD * 2) + (k0 + b_koff) * 2);
        #pragma unroll
        for (int mf = 0; mf < 4; mf++)
            #pragma unroll
            for (int nf = 0; nf < 4; nf++)
                mma_fp16(acc[mf][nf], a[mf], b[nf]);
    }

    // epilogue: float2 stores (lane quads cover 32B sectors)
    const int r = lane >> 2, c2 = (lane & 3) * 2;
    #pragma unroll
    for (int mf = 0; mf < 4; mf++) {
        size_t row_g = (size_t)bh * S_LEN + (size_t)mt * TM + wm * 64 + mf * 16 + r;
        #pragma unroll
        for (int nf = 0; nf < 4; nf++) {
            size_t col_g = (size_t)nt * TN + wn * 32 + nf * 8 + c2;
            *(float2*)(out + row_g * S_LEN + col_g) =
                make_float2(acc[mf][nf][0], acc[mf][nf][1]);
            *(float2*)(out + (row_g + 8) * S_LEN + col_g) =
                make_float2(acc[mf][nf][2], acc[mf][nf][3]);
        }
    }
}

// ---------------------------------------------------------------------------
// Pass 2: in-place row softmax (R1-proven: 88% DRAM, near roofline).
// ---------------------------------------------------------------------------
__device__ __forceinline__ float fast_exp_nonpos(float x) {
    float y = x * 1.4426950408889634f;
    float n = rintf(y);
    float f = y - n;
    float p = 1.5403530393e-4f;
    p = fmaf(p, f, 1.3333558146e-3f);
    p = fmaf(p, f, 9.6181291076e-3f);
    p = fmaf(p, f, 5.5504108664e-2f);
    p = fmaf(p, f, 2.4022650696e-1f);
    p = fmaf(p, f, 6.9314718056e-1f);
    p = fmaf(p, f, 1.0f);
    int e = (int)n + 127;
    float s = (e > 0) ? __int_as_float(e << 23) : 0.0f;
    return p * s;
}

__global__ __launch_bounds__(256, 1) void softmax_rows(float* __restrict__ out)
{
    __shared__ float red[8];
    float* p = out + (size_t)blockIdx.x * S_LEN;
    const int tid = threadIdx.x;
    const int lane = tid & 31;
    const int warp = tid >> 5;

    float4* p4 = (float4*)p;
    float4 v0 = p4[tid];
    float4 v1 = p4[tid + 256];

    float m = fmaxf(fmaxf(fmaxf(v0.x, v0.y), fmaxf(v0.z, v0.w)),
                    fmaxf(fmaxf(v1.x, v1.y), fmaxf(v1.z, v1.w)));
    #pragma unroll
    for (int o = 16; o > 0; o >>= 1)
        m = fmaxf(m, __shfl_xor_sync(0xffffffffu, m, o));
    if (lane == 0) red[warp] = m;
    __syncthreads();
    float M = red[0];
    #pragma unroll
    for (int i = 1; i < 8; i++) M = fmaxf(M, red[i]);
    __syncthreads();

    v0.x = fast_exp_nonpos(v0.x - M); v0.y = fast_exp_nonpos(v0.y - M);
    v0.z = fast_exp_nonpos(v0.z - M); v0.w = fast_exp_nonpos(v0.w - M);
    v1.x = fast_exp_nonpos(v1.x - M); v1.y = fast_exp_nonpos(v1.y - M);
    v1.z = fast_exp_nonpos(v1.z - M); v1.w = fast_exp_nonpos(v1.w - M);

    float s = ((v0.x + v0.y) + (v0.z + v0.w)) + ((v1.x + v1.y) + (v1.z + v1.w));
    #pragma unroll
    for (int o = 16; o > 0; o >>= 1)
        s += __shfl_xor_sync(0xffffffffu, s, o);
    if (lane == 0) red[warp] = s;
    __syncthreads();
    float Ssum = 0.0f;
    #pragma unroll
    for (int i = 0; i < 8; i++) Ssum += red[i];

    float inv = 1.0f / Ssum;
    v0.x *= inv; v0.y *= inv; v0.z *= inv; v0.w *= inv;
    v1.x *= inv; v1.y *= inv; v1.z *= inv; v1.w *= inv;
    p4[tid] = v0;
    p4[tid + 256] = v1;
}

// ---------------------------------------------------------------------------
extern "C" void kernel_launch(void* const* d_in, const int* in_sizes, int n_in,
                              void* d_out, int out_size)
{
    const float* keys      = (const float*)d_in[0];
    const float* queries   = (const float*)d_in[1];
    const float* pos_key   = (const float*)d_in[2];
    const float* pos_query = (const float*)d_in[3];
    float* out = (float*)d_out;

    // pass 0: fp16 convert
    const size_t prep_total = (size_t)BHN * S_LEN * KC;
    prep_fp16<<<(unsigned)((prep_total + 255) / 256), 256>>>(keys, queries, pos_key, pos_query);

    // pass 1: fp16 HMMA GEMM (single product, K=96)
    const int smem = 2 * TM * SPAD * sizeof(__half);   // 53248 B
    cudaFuncSetAttribute(score_gemm_hmma, cudaFuncAttributeMaxDynamicSharedMemorySize, smem);
    dim3 g(S_LEN / TN, S_LEN / TM, BHN);    // (16, 16, 64)
    score_gemm_hmma<<<g, 256, smem>>>(out);

    // pass 2: softmax
    softmax_rows<<<BHN * S_LEN, 256>>>(out);
}